// round 1
// baseline (speedup 1.0000x reference)
#include <cuda_runtime.h>
#include <math.h>

#define N_HEADS 16
#define HIDDEN  1024
#define HS      64
#define BATCH   2
#define SEQ     2048
#define M_ROWS  (BATCH * SEQ)      // 4096
#define N_COLS  (3 * HIDDEN)      // 3072

// Scratch for rearranged QKV: [s][b][h][t][d] = [3][2][16][2048][64]  (48 MB)
__device__ float g_qkv[(size_t)3 * BATCH * N_HEADS * SEQ * HS];

// ============================================================================
// Kernel 1: y = x @ W + b, with epilogue scatter implementing the module's
// flat reshape  [B,T,3D] -> view(3,B,T,hs,nh) -> permute(0,1,4,2,3).
// Index algebra: flat = r*3072 + c ; g = 3r + c/1024 ; e = c%1024
//   u = g/2048 (= 2s+b), t = g%2048, h = e%16, d = e/16
// ============================================================================
#define BM 128
#define BN 128
#define BK 16

__global__ __launch_bounds__(256) void qkv_gemm_kernel(
    const float* __restrict__ x, const float* __restrict__ W,
    const float* __restrict__ bias)
{
    __shared__ float As[BK][BM + 4];   // A transposed, padded
    __shared__ float Bs[BK][BN];

    const int tid = threadIdx.x;
    const int m0 = blockIdx.y * BM;
    const int n0 = blockIdx.x * BN;
    const int tx = tid & 15;          // 16 threads along N
    const int ty = tid >> 4;          // 16 threads along M

    float acc[8][8] = {};

    for (int kt = 0; kt < HIDDEN; kt += BK) {
        // Load A tile (128 x 16) transposed into As
        #pragma unroll
        for (int i = 0; i < 2; i++) {
            int f4 = tid + i * 256;
            int ar = f4 >> 2, ac = (f4 & 3) << 2;
            float4 v = *(const float4*)(x + (size_t)(m0 + ar) * HIDDEN + kt + ac);
            As[ac + 0][ar] = v.x; As[ac + 1][ar] = v.y;
            As[ac + 2][ar] = v.z; As[ac + 3][ar] = v.w;
        }
        // Load B tile (16 x 128)
        #pragma unroll
        for (int i = 0; i < 2; i++) {
            int f4 = tid + i * 256;
            int br = f4 >> 5, bc = (f4 & 31) << 2;
            *(float4*)&Bs[br][bc] =
                *(const float4*)(W + (size_t)(kt + br) * N_COLS + n0 + bc);
        }
        __syncthreads();

        #pragma unroll
        for (int kk = 0; kk < BK; kk++) {
            float ra[8], rb[8];
            *(float4*)&ra[0] = *(const float4*)&As[kk][ty * 8];
            *(float4*)&ra[4] = *(const float4*)&As[kk][ty * 8 + 4];
            *(float4*)&rb[0] = *(const float4*)&Bs[kk][tx * 8];
            *(float4*)&rb[4] = *(const float4*)&Bs[kk][tx * 8 + 4];
            #pragma unroll
            for (int i = 0; i < 8; i++)
                #pragma unroll
                for (int j = 0; j < 8; j++)
                    acc[i][j] += ra[i] * rb[j];
        }
        __syncthreads();
    }

    // Epilogue: bias add + scatter into [s][b][h][t][d] scratch
    #pragma unroll
    for (int i = 0; i < 8; i++) {
        int r = m0 + ty * 8 + i;
        #pragma unroll
        for (int j = 0; j < 8; j++) {
            int c = n0 + tx * 8 + j;
            float v = acc[i][j] + __ldg(&bias[c]);
            int g = 3 * r + (c >> 10);
            int e = c & 1023;
            int u = g >> 11;          // 2s + b
            int t = g & 2047;
            int h = e & 15;
            int d = e >> 4;
            g_qkv[(((size_t)(u * 16 + h)) * SEQ + t) * HS + d] = v;
        }
    }
}

// ============================================================================
// Kernel 2: flash attention (fp32), one CTA per (b, h, 64-row q-tile).
// Causal: only k-tiles kt <= qt; masking only on the diagonal tile.
// ============================================================================
#define SSTR 65      // padded smem row stride
#define BR   64
#define BC   64

__global__ __launch_bounds__(256) void attn_kernel(float* __restrict__ out)
{
    extern __shared__ float smf[];
    float* Qs = smf;                      // 64 x 65
    float* Ks = Qs + BR * SSTR;           // 64 x 65
    float* Vs = Ks + BC * SSTR;           // 64 x 65
    float* Ss = Vs + BC * SSTR;           // 64 x 65
    float* rm = Ss + BR * SSTR;           // 64 (row max)
    float* rl = rm + BR;                  // 64 (row sum)
    float* rs = rl + BR;                  // 64 (rescale factor)

    const int tid = threadIdx.x;
    const int qt = blockIdx.x;
    const int h  = blockIdx.y;
    const int b  = blockIdx.z;

    const size_t head_off = ((size_t)(b * 16 + h)) * SEQ * HS;
    const float* qp = g_qkv + head_off;
    const float* kp = g_qkv + (size_t)1 * BATCH * N_HEADS * SEQ * HS + head_off;
    const float* vp = g_qkv + (size_t)2 * BATCH * N_HEADS * SEQ * HS + head_off;

    const int q0 = qt * BR;

    // Load Q tile
    #pragma unroll
    for (int i = 0; i < 4; i++) {
        int f4 = tid + i * 256;
        int r = f4 >> 4, cv = (f4 & 15) << 2;
        float4 v = *(const float4*)(qp + (size_t)(q0 + r) * HS + cv);
        float* dst = Qs + r * SSTR + cv;
        dst[0] = v.x; dst[1] = v.y; dst[2] = v.z; dst[3] = v.w;
    }
    if (tid < BR) { rm[tid] = -1e30f; rl[tid] = 0.0f; }
    __syncthreads();

    const int tx = tid & 15;
    const int ty = tid >> 4;
    const float scale = 0.125f;   // 64^-0.5
    float acc[4][4] = {};

    for (int kt = 0; kt <= qt; kt++) {
        const int k0 = kt * BC;
        // Load K and V tiles
        #pragma unroll
        for (int i = 0; i < 4; i++) {
            int f4 = tid + i * 256;
            int r = f4 >> 4, cv = (f4 & 15) << 2;
            float4 kv4 = *(const float4*)(kp + (size_t)(k0 + r) * HS + cv);
            float* kd = Ks + r * SSTR + cv;
            kd[0] = kv4.x; kd[1] = kv4.y; kd[2] = kv4.z; kd[3] = kv4.w;
            float4 vv4 = *(const float4*)(vp + (size_t)(k0 + r) * HS + cv);
            float* vd = Vs + r * SSTR + cv;
            vd[0] = vv4.x; vd[1] = vv4.y; vd[2] = vv4.z; vd[3] = vv4.w;
        }
        __syncthreads();

        // S = Q @ K^T (4x4 microtile per thread)
        float sub[4][4] = {};
        #pragma unroll 8
        for (int kk = 0; kk < 64; kk++) {
            float qv[4], kv[4];
            #pragma unroll
            for (int i = 0; i < 4; i++) qv[i] = Qs[(ty * 4 + i) * SSTR + kk];
            #pragma unroll
            for (int j = 0; j < 4; j++) kv[j] = Ks[(tx * 4 + j) * SSTR + kk];
            #pragma unroll
            for (int i = 0; i < 4; i++)
                #pragma unroll
                for (int j = 0; j < 4; j++)
                    sub[i][j] += qv[i] * kv[j];
        }
        const bool diag = (kt == qt);
        #pragma unroll
        for (int i = 0; i < 4; i++) {
            int gi = q0 + ty * 4 + i;
            #pragma unroll
            for (int j = 0; j < 4; j++) {
                int gj = k0 + tx * 4 + j;
                float v = sub[i][j] * scale;
                if (diag && gj > gi) v = -1e30f;
                Ss[(ty * 4 + i) * SSTR + tx * 4 + j] = v;
            }
        }
        __syncthreads();

        // Online softmax: 4 threads per row
        {
            int row = tid >> 2, part = tid & 3;
            float* srow = Ss + row * SSTR + part * 16;
            float mloc = -1e30f;
            #pragma unroll
            for (int c = 0; c < 16; c++) mloc = fmaxf(mloc, srow[c]);
            mloc = fmaxf(mloc, __shfl_xor_sync(0xffffffffu, mloc, 1));
            mloc = fmaxf(mloc, __shfl_xor_sync(0xffffffffu, mloc, 2));
            float mold = rm[row];
            float mnew = fmaxf(mold, mloc);
            float ssum = 0.0f;
            #pragma unroll
            for (int c = 0; c < 16; c++) {
                float p = __expf(srow[c] - mnew);
                srow[c] = p;
                ssum += p;
            }
            ssum += __shfl_xor_sync(0xffffffffu, ssum, 1);
            ssum += __shfl_xor_sync(0xffffffffu, ssum, 2);
            if (part == 0) {
                float fac = __expf(mold - mnew);
                rm[row] = mnew;
                rs[row] = fac;
                rl[row] = rl[row] * fac + ssum;
            }
        }
        __syncthreads();

        // Rescale accumulator, then O += P @ V
        #pragma unroll
        for (int i = 0; i < 4; i++) {
            float fac = rs[ty * 4 + i];
            #pragma unroll
            for (int j = 0; j < 4; j++) acc[i][j] *= fac;
        }
        #pragma unroll 8
        for (int kk = 0; kk < 64; kk++) {
            float pv[4], vv[4];
            #pragma unroll
            for (int i = 0; i < 4; i++) pv[i] = Ss[(ty * 4 + i) * SSTR + kk];
            #pragma unroll
            for (int j = 0; j < 4; j++) vv[j] = Vs[kk * SSTR + tx * 4 + j];
            #pragma unroll
            for (int i = 0; i < 4; i++)
                #pragma unroll
                for (int j = 0; j < 4; j++)
                    acc[i][j] += pv[i] * vv[j];
        }
        __syncthreads();
    }

    // Write out[b][t][h*64 + d], normalized by row sum
    #pragma unroll
    for (int i = 0; i < 4; i++) {
        int t = q0 + ty * 4 + i;
        float inv = 1.0f / rl[ty * 4 + i];
        #pragma unroll
        for (int j = 0; j < 4; j++) {
            out[((size_t)(b * SEQ + t)) * HIDDEN + h * HS + tx * 4 + j] =
                acc[i][j] * inv;
        }
    }
}

// ============================================================================
// Launch
// ============================================================================
extern "C" void kernel_launch(void* const* d_in, const int* in_sizes, int n_in,
                              void* d_out, int out_size)
{
    const float* x    = (const float*)d_in[0];
    const float* W    = (const float*)d_in[1];
    const float* bias = (const float*)d_in[2];
    float* out = (float*)d_out;

    dim3 g1(N_COLS / BN, M_ROWS / BM);   // (24, 32)
    qkv_gemm_kernel<<<g1, 256>>>(x, W, bias);

    size_t smem = (size_t)(4 * BR * SSTR + 3 * BR) * sizeof(float);  // ~67 KB
    cudaFuncSetAttribute(attn_kernel,
                         cudaFuncAttributeMaxDynamicSharedMemorySize, (int)smem);
    dim3 g2(SEQ / BR, N_HEADS, BATCH);   // (32, 16, 2)
    attn_kernel<<<g2, 256, smem>>>(out);
}

// round 3
// speedup vs baseline: 1.3500x; 1.3500x over previous
#include <cuda_runtime.h>
#include <cstdint>
#include <math.h>

#define N_HEADS 16
#define HIDDEN  1024
#define HS      64
#define BATCH   2
#define SEQ     2048
#define M_ROWS  (BATCH * SEQ)      // 4096
#define N_COLS  (3 * HIDDEN)       // 3072

// Scratch for rearranged QKV: [s][b][h][t][d] = [3][2][16][2048][64]  (48 MB)
__device__ float g_qkv[(size_t)3 * BATCH * N_HEADS * SEQ * HS];

// ---------------------------------------------------------------------------
// Helpers
// ---------------------------------------------------------------------------
__device__ __forceinline__ uint32_t f2tf(float f) {
    uint32_t u;
    asm("cvt.rna.tf32.f32 %0, %1;" : "=r"(u) : "f"(f));
    return u;
}
__device__ __forceinline__ void mma_tf32(float* d, const uint32_t* a,
                                         const uint32_t* b, const float* c) {
    asm volatile(
        "mma.sync.aligned.m16n8k8.row.col.f32.tf32.tf32.f32 "
        "{%0,%1,%2,%3}, {%4,%5,%6,%7}, {%8,%9}, {%10,%11,%12,%13};"
        : "=f"(d[0]), "=f"(d[1]), "=f"(d[2]), "=f"(d[3])
        : "r"(a[0]), "r"(a[1]), "r"(a[2]), "r"(a[3]),
          "r"(b[0]), "r"(b[1]),
          "f"(c[0]), "f"(c[1]), "f"(c[2]), "f"(c[3]));
}

// ---------------------------------------------------------------------------
// Kernel 1: QKV GEMM via mma.sync tf32.  y = x @ W + b, epilogue scatter
// implementing flat reshape [B,T,3D]->view(3,B,T,hs,nh)->permute(0,1,4,2,3):
//   g = 3r + c/1024; e = c%1024; u=g>>11; t=g&2047; h=e&15; d=e>>4.
// CTA tile 128x128, BK=32, 8 warps (2M x 4N), warp tile 64x32.
// SMEM: A[2][128][32] swizzled, B[2][32][128] swizzled; epilogue reuses smem.
// ---------------------------------------------------------------------------
#define GBK   32
#define GNIT  (HIDDEN / GBK)          // 32
#define A_BUF 4096                    // floats per A stage
#define B_BUF 4096                    // floats per B stage
#define CSTR  132                     // epilogue smem stride
#define GEMM_SMEM_BYTES (CSTR * 128 * 4)   // 67584 >= 4*16KB buffers

__global__ void __launch_bounds__(256, 1) qkv_gemm_tc(
    const float* __restrict__ x, const float* __restrict__ W,
    const float* __restrict__ bias)
{
    extern __shared__ uint32_t smu[];
    // A stages at 0 / 4096, B stages at 8192 / 12288 (floats)
    const int tid  = threadIdx.x;
    const int lane = tid & 31;
    const int wid  = tid >> 5;
    const int wm   = wid & 1;          // 2 warps along M
    const int wn   = wid >> 1;         // 4 warps along N
    const int m0 = blockIdx.y * 128, n0 = blockIdx.x * 128;

    // Global load bases
    const int a_row = tid >> 3;                 // 0..31 (+32i)
    const int a_k4  = (tid & 7) << 2;           // 0..28
    const int b_krw = tid >> 5;                 // 0..7 (+8i)
    const int b_n4  = (tid & 31) << 2;          // 0..124
    const float* Ag = x + (size_t)(m0 + a_row) * HIDDEN + a_k4;
    const float* Bg = W + (size_t)b_krw * N_COLS + n0 + b_n4;

    // Swizzled smem store indices (in floats)
    const uint32_t a_st = a_row * 32 + (a_k4 ^ (((uint32_t)(a_row & 7)) << 2));
    const uint32_t b_st = b_krw * 128 + (b_n4 ^ (((uint32_t)(b_krw & 3)) << 3));

    float acc[4][4][4] = {};
    float4 av[4], bv[4];

    // Prefetch tile 0
    #pragma unroll
    for (int i = 0; i < 4; i++) {
        av[i] = *(const float4*)(Ag + (size_t)i * 32 * HIDDEN);
        bv[i] = *(const float4*)(Bg + (size_t)i * 8 * N_COLS);
    }

    const int lr = lane >> 2, lc = lane & 3;

    for (int it = 0; it < GNIT; ++it) {
        const uint32_t abase = (it & 1) ? A_BUF : 0;
        const uint32_t bbase = 2 * A_BUF + ((it & 1) ? B_BUF : 0);

        // Store prefetched tile (cvt to tf32)
        #pragma unroll
        for (int i = 0; i < 4; i++) {
            uint32_t* pa = smu + abase + a_st + i * 1024;
            pa[0] = f2tf(av[i].x); pa[1] = f2tf(av[i].y);
            pa[2] = f2tf(av[i].z); pa[3] = f2tf(av[i].w);
            uint32_t* pb = smu + bbase + b_st + i * 1024;
            pb[0] = f2tf(bv[i].x); pb[1] = f2tf(bv[i].y);
            pb[2] = f2tf(bv[i].z); pb[3] = f2tf(bv[i].w);
        }
        __syncthreads();

        // Prefetch next tile
        if (it + 1 < GNIT) {
            const float* Agn = Ag + (it + 1) * GBK;
            const float* Bgn = Bg + (size_t)(it + 1) * GBK * N_COLS;
            #pragma unroll
            for (int i = 0; i < 4; i++) {
                av[i] = *(const float4*)(Agn + (size_t)i * 32 * HIDDEN);
                bv[i] = *(const float4*)(Bgn + (size_t)i * 8 * N_COLS);
            }
        }

        // Compute on this buffer: 4 k-steps of k=8
        const uint32_t* Ab = smu + abase;
        const uint32_t* Bb = smu + bbase;
        #pragma unroll
        for (int ks = 0; ks < 4; ks++) {
            const int k0 = ks * 8;
            uint32_t af[4][4], bf[4][2];
            #pragma unroll
            for (int mf = 0; mf < 4; mf++) {
                const int r = wm * 64 + mf * 16 + lr;
                const uint32_t i0 = (uint32_t)(k0 + lc) ^ (((uint32_t)(r & 7)) << 2);
                const uint32_t base = r * 32;
                af[mf][0] = Ab[base + i0];
                af[mf][1] = Ab[base + 256 + i0];
                af[mf][2] = Ab[base + (i0 ^ 4)];
                af[mf][3] = Ab[base + 256 + (i0 ^ 4)];
            }
            #pragma unroll
            for (int nf = 0; nf < 4; nf++) {
                const int n = wn * 32 + nf * 8 + lr;
                const int kk = k0 + lc;
                const uint32_t bi = kk * 128 + ((uint32_t)n ^ (((uint32_t)(kk & 3)) << 3));
                bf[nf][0] = Bb[bi];
                bf[nf][1] = Bb[bi + 512];
            }
            #pragma unroll
            for (int mf = 0; mf < 4; mf++)
                #pragma unroll
                for (int nf = 0; nf < 4; nf++)
                    mma_tf32(acc[mf][nf], af[mf], bf[nf], acc[mf][nf]);
        }
        __syncthreads();   // buffer (it&1) free for overwrite 2 iters later
    }

    // ---- Epilogue: stage D through smem to coalesce the reshape-scatter ----
    float* Cs = (float*)smu;   // [128][CSTR], reuses all tile buffers
    #pragma unroll
    for (int mf = 0; mf < 4; mf++) {
        const int r = wm * 64 + mf * 16 + lr;
        #pragma unroll
        for (int nf = 0; nf < 4; nf++) {
            const int c = wn * 32 + nf * 8 + 2 * lc;
            *(float2*)&Cs[r * CSTR + c]       = make_float2(acc[mf][nf][0], acc[mf][nf][1]);
            *(float2*)&Cs[(r + 8) * CSTR + c] = make_float2(acc[mf][nf][2], acc[mf][nf][3]);
        }
    }
    __syncthreads();

    {
        const int rr = tid >> 1;        // 0..127 local row
        const int half = tid & 1;       // low/high 8 heads of the tile
        const int r = m0 + rr;
        const int g = 3 * r + (n0 >> 10);
        const int u = g >> 11, t = g & 2047;
        const int d0 = (n0 & 1023) >> 4;
        #pragma unroll
        for (int j = 0; j < 8; j++) {
            const int hh = half * 8 + j;
            float o[8];
            #pragma unroll
            for (int e = 0; e < 8; e++)
                o[e] = Cs[rr * CSTR + hh + 16 * e] + __ldg(&bias[n0 + hh + 16 * e]);
            float* dst = g_qkv + (((size_t)(u * 16 + hh)) * SEQ + t) * HS + d0;
            *(float4*)dst       = make_float4(o[0], o[1], o[2], o[3]);
            *(float4*)(dst + 4) = make_float4(o[4], o[5], o[6], o[7]);
        }
    }
}

// ---------------------------------------------------------------------------
// Kernel 2: flash attention (fp32 SIMT) — unchanged from passing round 1.
// ---------------------------------------------------------------------------
#define SSTR 65
#define BR   64
#define BC   64

__global__ __launch_bounds__(256) void attn_kernel(float* __restrict__ out) {
    extern __shared__ float smf[];
    float* Qs = smf;
    float* Ks = Qs + BR * SSTR;
    float* Vs = Ks + BC * SSTR;
    float* Ss = Vs + BC * SSTR;
    float* rm = Ss + BR * SSTR;
    float* rl = rm + BR;
    float* rs = rl + BR;

    const int tid = threadIdx.x;
    const int qt = blockIdx.x;
    const int h  = blockIdx.y;
    const int b  = blockIdx.z;

    const size_t head_off = ((size_t)(b * 16 + h)) * SEQ * HS;
    const float* qp = g_qkv + head_off;
    const float* kp = g_qkv + (size_t)1 * BATCH * N_HEADS * SEQ * HS + head_off;
    const float* vp = g_qkv + (size_t)2 * BATCH * N_HEADS * SEQ * HS + head_off;

    const int q0 = qt * BR;

    #pragma unroll
    for (int i = 0; i < 4; i++) {
        int f4 = tid + i * 256;
        int r = f4 >> 4, cv = (f4 & 15) << 2;
        float4 v = *(const float4*)(qp + (size_t)(q0 + r) * HS + cv);
        float* dst = Qs + r * SSTR + cv;
        dst[0] = v.x; dst[1] = v.y; dst[2] = v.z; dst[3] = v.w;
    }
    if (tid < BR) { rm[tid] = -1e30f; rl[tid] = 0.0f; }
    __syncthreads();

    const int tx = tid & 15;
    const int ty = tid >> 4;
    const float scale = 0.125f;
    float acc[4][4] = {};

    for (int kt = 0; kt <= qt; kt++) {
        const int k0 = kt * BC;
        #pragma unroll
        for (int i = 0; i < 4; i++) {
            int f4 = tid + i * 256;
            int r = f4 >> 4, cv = (f4 & 15) << 2;
            float4 kv4 = *(const float4*)(kp + (size_t)(k0 + r) * HS + cv);
            float* kd = Ks + r * SSTR + cv;
            kd[0] = kv4.x; kd[1] = kv4.y; kd[2] = kv4.z; kd[3] = kv4.w;
            float4 vv4 = *(const float4*)(vp + (size_t)(k0 + r) * HS + cv);
            float* vd = Vs + r * SSTR + cv;
            vd[0] = vv4.x; vd[1] = vv4.y; vd[2] = vv4.z; vd[3] = vv4.w;
        }
        __syncthreads();

        float sub[4][4] = {};
        #pragma unroll 8
        for (int kk = 0; kk < 64; kk++) {
            float qv[4], kv[4];
            #pragma unroll
            for (int i = 0; i < 4; i++) qv[i] = Qs[(ty * 4 + i) * SSTR + kk];
            #pragma unroll
            for (int j = 0; j < 4; j++) kv[j] = Ks[(tx * 4 + j) * SSTR + kk];
            #pragma unroll
            for (int i = 0; i < 4; i++)
                #pragma unroll
                for (int j = 0; j < 4; j++)
                    sub[i][j] += qv[i] * kv[j];
        }
        const bool diag = (kt == qt);
        #pragma unroll
        for (int i = 0; i < 4; i++) {
            int gi = q0 + ty * 4 + i;
            #pragma unroll
            for (int j = 0; j < 4; j++) {
                int gj = k0 + tx * 4 + j;
                float v = sub[i][j] * scale;
                if (diag && gj > gi) v = -1e30f;
                Ss[(ty * 4 + i) * SSTR + tx * 4 + j] = v;
            }
        }
        __syncthreads();

        {
            int row = tid >> 2, part = tid & 3;
            float* srow = Ss + row * SSTR + part * 16;
            float mloc = -1e30f;
            #pragma unroll
            for (int c = 0; c < 16; c++) mloc = fmaxf(mloc, srow[c]);
            mloc = fmaxf(mloc, __shfl_xor_sync(0xffffffffu, mloc, 1));
            mloc = fmaxf(mloc, __shfl_xor_sync(0xffffffffu, mloc, 2));
            float mold = rm[row];
            float mnew = fmaxf(mold, mloc);
            float ssum = 0.0f;
            #pragma unroll
            for (int c = 0; c < 16; c++) {
                float p = __expf(srow[c] - mnew);
                srow[c] = p;
                ssum += p;
            }
            ssum += __shfl_xor_sync(0xffffffffu, ssum, 1);
            ssum += __shfl_xor_sync(0xffffffffu, ssum, 2);
            if (part == 0) {
                float fac = __expf(mold - mnew);
                rm[row] = mnew;
                rs[row] = fac;
                rl[row] = rl[row] * fac + ssum;
            }
        }
        __syncthreads();

        #pragma unroll
        for (int i = 0; i < 4; i++) {
            float fac = rs[ty * 4 + i];
            #pragma unroll
            for (int j = 0; j < 4; j++) acc[i][j] *= fac;
        }
        #pragma unroll 8
        for (int kk = 0; kk < 64; kk++) {
            float pv[4], vv[4];
            #pragma unroll
            for (int i = 0; i < 4; i++) pv[i] = Ss[(ty * 4 + i) * SSTR + kk];
            #pragma unroll
            for (int j = 0; j < 4; j++) vv[j] = Vs[kk * SSTR + tx * 4 + j];
            #pragma unroll
            for (int i = 0; i < 4; i++)
                #pragma unroll
                for (int j = 0; j < 4; j++)
                    acc[i][j] += pv[i] * vv[j];
        }
        __syncthreads();
    }

    #pragma unroll
    for (int i = 0; i < 4; i++) {
        int t = q0 + ty * 4 + i;
        float inv = 1.0f / rl[ty * 4 + i];
        #pragma unroll
        for (int j = 0; j < 4; j++) {
            out[((size_t)(b * SEQ + t)) * HIDDEN + h * HS + tx * 4 + j] =
                acc[i][j] * inv;
        }
    }
}

// ---------------------------------------------------------------------------
// Launch
// ---------------------------------------------------------------------------
extern "C" void kernel_launch(void* const* d_in, const int* in_sizes, int n_in,
                              void* d_out, int out_size) {
    const float* x    = (const float*)d_in[0];
    const float* W    = (const float*)d_in[1];
    const float* bias = (const float*)d_in[2];
    float* out = (float*)d_out;

    cudaFuncSetAttribute(qkv_gemm_tc,
                         cudaFuncAttributeMaxDynamicSharedMemorySize,
                         GEMM_SMEM_BYTES);
    qkv_gemm_tc<<<dim3(N_COLS / 128, M_ROWS / 128), 256, GEMM_SMEM_BYTES>>>(
        x, W, bias);

    size_t smem = (size_t)(4 * BR * SSTR + 3 * BR) * sizeof(float);
    cudaFuncSetAttribute(attn_kernel,
                         cudaFuncAttributeMaxDynamicSharedMemorySize, (int)smem);
    attn_kernel<<<dim3(SEQ / BR, N_HEADS, BATCH), 256, smem>>>(out);
}

// round 5
// speedup vs baseline: 2.4664x; 1.8270x over previous
#include <cuda_runtime.h>
#include <cstdint>
#include <math.h>

#define N_HEADS 16
#define HIDDEN  1024
#define HS      64
#define BATCH   2
#define SEQ     2048
#define M_ROWS  (BATCH * SEQ)      // 4096
#define N_COLS  (3 * HIDDEN)       // 3072

// Scratch QKV, flat [u=2s+b][h][...]:
//   Q (u=0,1) and V (u=4,5): [t][d] row-major
//   K (u=2,3):               [d][t] row-major  (K^T, for mma B operand)
__device__ float g_qkv[(size_t)6 * N_HEADS * SEQ * HS];

// ---------------------------------------------------------------------------
// Helpers
// ---------------------------------------------------------------------------
__device__ __forceinline__ uint32_t f2tf(float f) {
    uint32_t u;
    asm("cvt.rna.tf32.f32 %0, %1;" : "=r"(u) : "f"(f));
    return u;
}
__device__ __forceinline__ void mma_tf32(float* d, const uint32_t* a,
                                         const uint32_t* b, const float* c) {
    asm volatile(
        "mma.sync.aligned.m16n8k8.row.col.f32.tf32.tf32.f32 "
        "{%0,%1,%2,%3}, {%4,%5,%6,%7}, {%8,%9}, {%10,%11,%12,%13};"
        : "=f"(d[0]), "=f"(d[1]), "=f"(d[2]), "=f"(d[3])
        : "r"(a[0]), "r"(a[1]), "r"(a[2]), "r"(a[3]),
          "r"(b[0]), "r"(b[1]),
          "f"(c[0]), "f"(c[1]), "f"(c[2]), "f"(c[3]));
}
__device__ __forceinline__ void split_tf32(float v, uint32_t& hi, uint32_t& lo) {
    hi = f2tf(v);
    lo = f2tf(v - __uint_as_float(hi));
}

// ---------------------------------------------------------------------------
// Kernel 1: QKV GEMM via mma.sync tf32; epilogue writes K third d-major.
// Reshape algebra: g = 3r + c/1024; e = c%1024; u=g>>11; t=g&2047;
// h=e&15; d=e>>4.
// ---------------------------------------------------------------------------
#define GBK   32
#define GNIT  (HIDDEN / GBK)          // 32
#define A_BUF 4096
#define B_BUF 4096
#define CSTR  132
#define GEMM_SMEM_BYTES (CSTR * 128 * 4)

__global__ void __launch_bounds__(256, 1) qkv_gemm_tc(
    const float* __restrict__ x, const float* __restrict__ W,
    const float* __restrict__ bias)
{
    extern __shared__ uint32_t smu[];
    const int tid  = threadIdx.x;
    const int lane = tid & 31;
    const int wid  = tid >> 5;
    const int wm   = wid & 1;
    const int wn   = wid >> 1;
    const int m0 = blockIdx.y * 128, n0 = blockIdx.x * 128;

    const int a_row = tid >> 3;
    const int a_k4  = (tid & 7) << 2;
    const int b_krw = tid >> 5;
    const int b_n4  = (tid & 31) << 2;
    const float* Ag = x + (size_t)(m0 + a_row) * HIDDEN + a_k4;
    const float* Bg = W + (size_t)b_krw * N_COLS + n0 + b_n4;

    const uint32_t a_st = a_row * 32 + (a_k4 ^ (((uint32_t)(a_row & 7)) << 2));
    const uint32_t b_st = b_krw * 128 + (b_n4 ^ (((uint32_t)(b_krw & 3)) << 3));

    float acc[4][4][4] = {};
    float4 av[4], bv[4];

    #pragma unroll
    for (int i = 0; i < 4; i++) {
        av[i] = *(const float4*)(Ag + (size_t)i * 32 * HIDDEN);
        bv[i] = *(const float4*)(Bg + (size_t)i * 8 * N_COLS);
    }

    const int lr = lane >> 2, lc = lane & 3;

    for (int it = 0; it < GNIT; ++it) {
        const uint32_t abase = (it & 1) ? A_BUF : 0;
        const uint32_t bbase = 2 * A_BUF + ((it & 1) ? B_BUF : 0);

        #pragma unroll
        for (int i = 0; i < 4; i++) {
            uint32_t* pa = smu + abase + a_st + i * 1024;
            pa[0] = f2tf(av[i].x); pa[1] = f2tf(av[i].y);
            pa[2] = f2tf(av[i].z); pa[3] = f2tf(av[i].w);
            uint32_t* pb = smu + bbase + b_st + i * 1024;
            pb[0] = f2tf(bv[i].x); pb[1] = f2tf(bv[i].y);
            pb[2] = f2tf(bv[i].z); pb[3] = f2tf(bv[i].w);
        }
        __syncthreads();

        if (it + 1 < GNIT) {
            const float* Agn = Ag + (it + 1) * GBK;
            const float* Bgn = Bg + (size_t)(it + 1) * GBK * N_COLS;
            #pragma unroll
            for (int i = 0; i < 4; i++) {
                av[i] = *(const float4*)(Agn + (size_t)i * 32 * HIDDEN);
                bv[i] = *(const float4*)(Bgn + (size_t)i * 8 * N_COLS);
            }
        }

        const uint32_t* Ab = smu + abase;
        const uint32_t* Bb = smu + bbase;
        #pragma unroll
        for (int ks = 0; ks < 4; ks++) {
            const int k0 = ks * 8;
            uint32_t af[4][4], bf[4][2];
            #pragma unroll
            for (int mf = 0; mf < 4; mf++) {
                const int r = wm * 64 + mf * 16 + lr;
                const uint32_t i0 = (uint32_t)(k0 + lc) ^ (((uint32_t)(r & 7)) << 2);
                const uint32_t base = r * 32;
                af[mf][0] = Ab[base + i0];
                af[mf][1] = Ab[base + 256 + i0];
                af[mf][2] = Ab[base + (i0 ^ 4)];
                af[mf][3] = Ab[base + 256 + (i0 ^ 4)];
            }
            #pragma unroll
            for (int nf = 0; nf < 4; nf++) {
                const int n = wn * 32 + nf * 8 + lr;
                const int kk = k0 + lc;
                const uint32_t bi = kk * 128 + ((uint32_t)n ^ (((uint32_t)(kk & 3)) << 3));
                bf[nf][0] = Bb[bi];
                bf[nf][1] = Bb[bi + 512];
            }
            #pragma unroll
            for (int mf = 0; mf < 4; mf++)
                #pragma unroll
                for (int nf = 0; nf < 4; nf++)
                    mma_tf32(acc[mf][nf], af[mf], bf[nf], acc[mf][nf]);
        }
        __syncthreads();
    }

    // ---- Epilogue via smem ----
    float* Cs = (float*)smu;
    #pragma unroll
    for (int mf = 0; mf < 4; mf++) {
        const int r = wm * 64 + mf * 16 + lr;
        #pragma unroll
        for (int nf = 0; nf < 4; nf++) {
            const int c = wn * 32 + nf * 8 + 2 * lc;
            *(float2*)&Cs[r * CSTR + c]       = make_float2(acc[mf][nf][0], acc[mf][nf][1]);
            *(float2*)&Cs[(r + 8) * CSTR + c] = make_float2(acc[mf][nf][2], acc[mf][nf][3]);
        }
    }
    __syncthreads();

    {
        const int rr = tid >> 1;
        const int half = tid & 1;
        const int r = m0 + rr;
        const int g = 3 * r + (n0 >> 10);
        const int u = g >> 11, t = g & 2047;
        const int d0 = (n0 & 1023) >> 4;
        const bool isK = ((u >> 1) == 1);
        #pragma unroll
        for (int j = 0; j < 8; j++) {
            const int hh = half * 8 + j;
            float o[8];
            #pragma unroll
            for (int e = 0; e < 8; e++)
                o[e] = Cs[rr * CSTR + hh + 16 * e] + __ldg(&bias[n0 + hh + 16 * e]);
            float* base = g_qkv + (size_t)(u * 16 + hh) * (SEQ * HS);
            if (isK) {
                #pragma unroll
                for (int e = 0; e < 8; e++)
                    base[(size_t)(d0 + e) * SEQ + t] = o[e];
            } else {
                float* dst = base + (size_t)t * HS + d0;
                *(float4*)dst       = make_float4(o[0], o[1], o[2], o[3]);
                *(float4*)(dst + 4) = make_float4(o[4], o[5], o[6], o[7]);
            }
        }
    }
}

// ---------------------------------------------------------------------------
// Kernel 2: flash attention via mma.sync tf32, split-precision.
// BR=128 rows/CTA, 8 warps (16 rows each), BC=64 keys per tile.
// ---------------------------------------------------------------------------
#define ATT_SMEM_U32 28672   // 8192*2 + 4096*3
#define ATT_SMEM_BYTES (ATT_SMEM_U32 * 4)

__global__ void __launch_bounds__(256, 1) attn_mma(float* __restrict__ out) {
    extern __shared__ uint32_t sm[];
    uint32_t* Qhi = sm;                 // 8192
    uint32_t* Qlo = sm + 8192;          // 8192
    uint32_t* Khi = sm + 16384;         // 4096
    uint32_t* Klo = sm + 20480;         // 4096
    uint32_t* Vs  = sm + 24576;         // 4096

    const int tid  = threadIdx.x;
    const int lane = tid & 31;
    const int w    = tid >> 5;          // warp 0..7, rows [16w,16w+16)
    const int lr   = lane >> 2, lc = lane & 3;
    const int qtile = (int)(gridDim.x - 1) - (int)blockIdx.x;  // long CTAs first
    const int h = blockIdx.y, b = blockIdx.z;
    const int q0 = qtile * 128;

    const float* qg  = g_qkv + (size_t)(b * 16 + h) * (SEQ * HS);            // [t][d]
    const float* ktg = g_qkv + (size_t)((2 + b) * 16 + h) * (SEQ * HS);      // [d][t]
    const float* vg  = g_qkv + (size_t)((4 + b) * 16 + h) * (SEQ * HS);      // [t][d]

    // ---- Load Q tile (scaled by 2^-3, exact), split hi/lo ----
    #pragma unroll
    for (int i = 0; i < 8; i++) {
        int f = tid + i * 256;
        int r = f >> 4, d4 = (f & 15) << 2;
        float4 v = *(const float4*)(qg + (size_t)(q0 + r) * HS + d4);
        v.x *= 0.125f; v.y *= 0.125f; v.z *= 0.125f; v.w *= 0.125f;
        uint32_t idx = r * 64 + ((uint32_t)d4 ^ (((uint32_t)(r & 7)) << 2));
        uint4 hi, lo;
        split_tf32(v.x, hi.x, lo.x); split_tf32(v.y, hi.y, lo.y);
        split_tf32(v.z, hi.z, lo.z); split_tf32(v.w, hi.w, lo.w);
        *(uint4*)&Qhi[idx] = hi;
        *(uint4*)&Qlo[idx] = lo;
    }

    float oacc[8][4];
    #pragma unroll
    for (int j = 0; j < 8; j++)
        #pragma unroll
        for (int k = 0; k < 4; k++) oacc[j][k] = 0.0f;
    float m0 = -1e30f, m1 = -1e30f, l0 = 0.0f, l1 = 0.0f;

    const int nkt = 2 * qtile + 2;
    for (int kt = 0; kt < nkt; kt++) {
        const int k0g = kt * 64;

        // Load FULL 64-row K^T and V tiles (4 x 256 threads x float4 each)
        float4 kv[4][2];
        uint32_t kidx[4];
        #pragma unroll
        for (int i = 0; i < 4; i++) {
            int f = tid + i * 256;
            int rr = f >> 4, c4 = (f & 15) << 2;
            kv[i][0] = *(const float4*)(ktg + (size_t)rr * SEQ + k0g + c4);
            kv[i][1] = *(const float4*)(vg + (size_t)(k0g + rr) * HS + c4);
            kidx[i] = rr * 64 + ((uint32_t)c4 ^ (((uint32_t)(rr & 3)) << 3));
        }
        __syncthreads();   // everyone done reading previous K/V
        #pragma unroll
        for (int i = 0; i < 4; i++) {
            uint4 hi, lo;
            split_tf32(kv[i][0].x, hi.x, lo.x); split_tf32(kv[i][0].y, hi.y, lo.y);
            split_tf32(kv[i][0].z, hi.z, lo.z); split_tf32(kv[i][0].w, hi.w, lo.w);
            *(uint4*)&Khi[kidx[i]] = hi;
            *(uint4*)&Klo[kidx[i]] = lo;
            uint4 vv;
            vv.x = f2tf(kv[i][1].x); vv.y = f2tf(kv[i][1].y);
            vv.z = f2tf(kv[i][1].z); vv.w = f2tf(kv[i][1].w);
            *(uint4*)&Vs[kidx[i]] = vv;
        }
        __syncthreads();   // tiles visible

        // Full-skip: all cols of this tile above all rows of this warp
        if (k0g > q0 + 16 * w + 15) continue;

        // ---- S = Q K^T (split 3-mma) ----
        float sacc[8][4];
        #pragma unroll
        for (int j = 0; j < 8; j++)
            #pragma unroll
            for (int k = 0; k < 4; k++) sacc[j][k] = 0.0f;

        #pragma unroll
        for (int ks = 0; ks < 8; ks++) {
            const int k8 = ks * 8;
            uint32_t ahi[4], alo[4];
            {
                const int r = 16 * w + lr;
                const uint32_t i0 = (uint32_t)(k8 + lc) ^ (((uint32_t)(r & 7)) << 2);
                const uint32_t base = r * 64;
                ahi[0] = Qhi[base + i0];       alo[0] = Qlo[base + i0];
                ahi[1] = Qhi[base + 512 + i0]; alo[1] = Qlo[base + 512 + i0];
                ahi[2] = Qhi[base + (i0 ^ 4)]; alo[2] = Qlo[base + (i0 ^ 4)];
                ahi[3] = Qhi[base + 512 + (i0 ^ 4)]; alo[3] = Qlo[base + 512 + (i0 ^ 4)];
            }
            const uint32_t kbase = (uint32_t)(k8 + lc) * 64;
            #pragma unroll
            for (int j = 0; j < 8; j++) {
                const uint32_t bi = kbase + ((uint32_t)(8 * j + lr) ^ (((uint32_t)lc) << 3));
                uint32_t bh[2] = { Khi[bi], Khi[bi + 256] };
                mma_tf32(sacc[j], ahi, bh, sacc[j]);
                mma_tf32(sacc[j], alo, bh, sacc[j]);
                uint32_t bl[2] = { Klo[bi], Klo[bi + 256] };
                mma_tf32(sacc[j], ahi, bl, sacc[j]);
            }
        }

        // ---- Causal mask (only near diagonal) ----
        const int row0 = q0 + 16 * w + lr;
        if (k0g + 63 > q0 + 16 * w) {
            #pragma unroll
            for (int j = 0; j < 8; j++) {
                const int c0 = k0g + 8 * j + 2 * lc;
                if (c0 > row0)         sacc[j][0] = -1e30f;
                if (c0 + 1 > row0)     sacc[j][1] = -1e30f;
                if (c0 > row0 + 8)     sacc[j][2] = -1e30f;
                if (c0 + 1 > row0 + 8) sacc[j][3] = -1e30f;
            }
        }

        // ---- Online softmax (registers + quad shuffles) ----
        float ml0 = -1e30f, ml1 = -1e30f;
        #pragma unroll
        for (int j = 0; j < 8; j++) {
            ml0 = fmaxf(ml0, fmaxf(sacc[j][0], sacc[j][1]));
            ml1 = fmaxf(ml1, fmaxf(sacc[j][2], sacc[j][3]));
        }
        ml0 = fmaxf(ml0, __shfl_xor_sync(0xffffffffu, ml0, 1));
        ml0 = fmaxf(ml0, __shfl_xor_sync(0xffffffffu, ml0, 2));
        ml1 = fmaxf(ml1, __shfl_xor_sync(0xffffffffu, ml1, 1));
        ml1 = fmaxf(ml1, __shfl_xor_sync(0xffffffffu, ml1, 2));

        const float mn0 = fmaxf(m0, ml0), mn1 = fmaxf(m1, ml1);
        const float fac0 = __expf(m0 - mn0), fac1 = __expf(m1 - mn1);
        float ls0 = 0.0f, ls1 = 0.0f;
        #pragma unroll
        for (int j = 0; j < 8; j++) {
            float p0 = __expf(sacc[j][0] - mn0);
            float p1 = __expf(sacc[j][1] - mn0);
            float p2 = __expf(sacc[j][2] - mn1);
            float p3 = __expf(sacc[j][3] - mn1);
            sacc[j][0] = p0; sacc[j][1] = p1; sacc[j][2] = p2; sacc[j][3] = p3;
            ls0 += p0 + p1; ls1 += p2 + p3;
        }
        ls0 += __shfl_xor_sync(0xffffffffu, ls0, 1);
        ls0 += __shfl_xor_sync(0xffffffffu, ls0, 2);
        ls1 += __shfl_xor_sync(0xffffffffu, ls1, 1);
        ls1 += __shfl_xor_sync(0xffffffffu, ls1, 2);
        l0 = l0 * fac0 + ls0;
        l1 = l1 * fac1 + ls1;
        m0 = mn0; m1 = mn1;

        #pragma unroll
        for (int j = 0; j < 8; j++) {
            oacc[j][0] *= fac0; oacc[j][1] *= fac0;
            oacc[j][2] *= fac1; oacc[j][3] *= fac1;
        }

        // ---- O += P V : shuffle D-frag -> A-frag, split P, single-tf32 V ----
        const int srcA = (lr << 2) + (lc >> 1);
        const int srcB = srcA + 2;
        const int sel  = lc & 1;
        #pragma unroll
        for (int ks = 0; ks < 8; ks++) {
            float x0 = __shfl_sync(0xffffffffu, sacc[ks][0], srcA);
            float x1 = __shfl_sync(0xffffffffu, sacc[ks][1], srcA);
            float y0 = __shfl_sync(0xffffffffu, sacc[ks][2], srcA);
            float y1 = __shfl_sync(0xffffffffu, sacc[ks][3], srcA);
            float z0 = __shfl_sync(0xffffffffu, sacc[ks][0], srcB);
            float z1 = __shfl_sync(0xffffffffu, sacc[ks][1], srcB);
            float w0 = __shfl_sync(0xffffffffu, sacc[ks][2], srcB);
            float w1 = __shfl_sync(0xffffffffu, sacc[ks][3], srcB);
            float pa0 = sel ? x1 : x0;
            float pa1 = sel ? y1 : y0;
            float pa2 = sel ? z1 : z0;
            float pa3 = sel ? w1 : w0;
            uint32_t phi[4], plo[4];
            split_tf32(pa0, phi[0], plo[0]);
            split_tf32(pa1, phi[1], plo[1]);
            split_tf32(pa2, phi[2], plo[2]);
            split_tf32(pa3, phi[3], plo[3]);

            const uint32_t vbase = (uint32_t)(ks * 8 + lc) * 64;
            #pragma unroll
            for (int j = 0; j < 8; j++) {
                const uint32_t bi = vbase + ((uint32_t)(8 * j + lr) ^ (((uint32_t)lc) << 3));
                uint32_t vb[2] = { Vs[bi], Vs[bi + 256] };
                mma_tf32(oacc[j], phi, vb, oacc[j]);
                mma_tf32(oacc[j], plo, vb, oacc[j]);
            }
        }
    }

    // ---- Write O / l ----
    const float inv0 = 1.0f / l0, inv1 = 1.0f / l1;
    const int row = q0 + 16 * w + lr;
    float* ob0 = out + ((size_t)(b * SEQ + row)) * HIDDEN + h * HS;
    float* ob1 = out + ((size_t)(b * SEQ + row + 8)) * HIDDEN + h * HS;
    #pragma unroll
    for (int j = 0; j < 8; j++) {
        const int c = 8 * j + 2 * lc;
        *(float2*)(ob0 + c) = make_float2(oacc[j][0] * inv0, oacc[j][1] * inv0);
        *(float2*)(ob1 + c) = make_float2(oacc[j][2] * inv1, oacc[j][3] * inv1);
    }
}

// ---------------------------------------------------------------------------
// Launch
// ---------------------------------------------------------------------------
extern "C" void kernel_launch(void* const* d_in, const int* in_sizes, int n_in,
                              void* d_out, int out_size) {
    const float* x    = (const float*)d_in[0];
    const float* W    = (const float*)d_in[1];
    const float* bias = (const float*)d_in[2];
    float* out = (float*)d_out;

    cudaFuncSetAttribute(qkv_gemm_tc,
                         cudaFuncAttributeMaxDynamicSharedMemorySize,
                         GEMM_SMEM_BYTES);
    qkv_gemm_tc<<<dim3(N_COLS / 128, M_ROWS / 128), 256, GEMM_SMEM_BYTES>>>(
        x, W, bias);

    cudaFuncSetAttribute(attn_mma,
                         cudaFuncAttributeMaxDynamicSharedMemorySize,
                         ATT_SMEM_BYTES);
    attn_mma<<<dim3(SEQ / 128, N_HEADS, BATCH), 256, ATT_SMEM_BYTES>>>(out);
}